// round 1
// baseline (speedup 1.0000x reference)
#include <cuda_runtime.h>
#include <cstdint>
#include <math.h>

#define NB 32
#define NT 64
#define NI 64
#define NH 512
#define NO 16
#define ICH 16   // i-chunks per step for the big pass
#define IPT 32   // i per chunk (NH/ICH)

// ---------------- persistent device state (no allocations allowed) -------------
__device__ float g_Scum[NB*NH*NH];          // cumulative raw syn normals (33.5MB)
__device__ float g_A[(NT+1)*NB*NH];         // a_t = tanh(h_t) history
__device__ float g_h[NB*NH];                // hidden state
__device__ float g_rpart[ICH*NB*NH];        // partial sums of a^T Scum
__device__ float g_neu[NB*NH];              // neuron noise (raw normals)
__device__ unsigned g_keys[NT][4];          // per-step k1,k2 (threefry keys)
__device__ float g_whhT[NH*NH];             // w_hh transposed (i-major)
__device__ float g_winT[NI*NH];             // w_in transposed (k-major)

// ---------------- JAX threefry2x32 (exact) ------------------------------------
__device__ __forceinline__ void tf2x32(unsigned k0, unsigned k1, unsigned x0, unsigned x1,
                                       unsigned &o0, unsigned &o1) {
    unsigned k2 = k0 ^ k1 ^ 0x1BD11BDAu;
    x0 += k0; x1 += k1;
#define TFR(r) { x0 += x1; x1 = __funnelshift_l(x1, x1, r); x1 ^= x0; }
    TFR(13) TFR(15) TFR(26) TFR(6)
    x0 += k1; x1 += k2 + 1u;
    TFR(17) TFR(29) TFR(16) TFR(24)
    x0 += k2; x1 += k0 + 2u;
    TFR(13) TFR(15) TFR(26) TFR(6)
    x0 += k0; x1 += k1 + 3u;
    TFR(17) TFR(29) TFR(16) TFR(24)
    x0 += k1; x1 += k2 + 4u;
    TFR(13) TFR(15) TFR(26) TFR(6)
    x0 += k2; x1 += k0 + 5u;
#undef TFR
    o0 = x0; o1 = x1;
}

// XLA ErfInv (f32, Giles polynomial)
__device__ __forceinline__ float erfinv_xla(float x) {
    float w = -__logf(fmaf(-x, x, 1.0f));
    float p;
    if (w < 5.0f) {
        w = w - 2.5f;
        p = 2.81022636e-08f;
        p = fmaf(p, w, 3.43273939e-07f);
        p = fmaf(p, w, -3.5233877e-06f);
        p = fmaf(p, w, -4.39150654e-06f);
        p = fmaf(p, w, 0.00021858087f);
        p = fmaf(p, w, -0.00125372503f);
        p = fmaf(p, w, -0.00417768164f);
        p = fmaf(p, w, 0.246640727f);
        p = fmaf(p, w, 1.50140941f);
    } else {
        w = sqrtf(w) - 3.0f;
        p = -0.000200214257f;
        p = fmaf(p, w, 0.000100950558f);
        p = fmaf(p, w, 0.00134934322f);
        p = fmaf(p, w, -0.00367342844f);
        p = fmaf(p, w, 0.00573950773f);
        p = fmaf(p, w, -0.0076224613f);
        p = fmaf(p, w, 0.00943887047f);
        p = fmaf(p, w, 1.00167406f);
        p = fmaf(p, w, 2.83297682f);
    }
    return p * x;
}

// JAX normal(f32): u = bits->[0,1), scaled to [-1+eps, 1), sqrt(2)*erfinv(u)
__device__ __forceinline__ float bits_to_normal(unsigned bits) {
    float f = __uint_as_float((bits >> 9) | 0x3f800000u) - 1.0f;
    float u = fmaf(f, 2.0f, -0.99999994f);
    u = fmaxf(-0.99999994f, u);
    return 1.41421356f * erfinv_xla(u);
}

// ---------------- init: keys, transposes, h/a0 --------------------------------
__global__ void k_init(const float* __restrict__ hidden,
                       const float* __restrict__ w_hh,
                       const float* __restrict__ w_in) {
    int idx = blockIdx.x * blockDim.x + threadIdx.x;
    if (idx < NH*NH) {                       // w_hhT[i][j] = w_hh[j][i]
        int jj = idx / NH, ii = idx % NH;
        g_whhT[ii*NH + jj] = w_hh[idx];
    }
    if (idx < NI*NH) {                       // w_inT[k][j] = w_in[j][k]
        int jj = idx / NI, kk = idx % NI;
        g_winT[kk*NH + jj] = w_in[idx];
    }
    if (idx < NB*NH) {
        float h = hidden[idx];
        g_h[idx] = h;
        g_A[idx] = tanhf(h);                 // a_0
    }
    if (idx < NT) {
        // fold_in(key(1234), t) -> split -> (k1, k2); partitionable foldlike split
        unsigned f0, f1, a0, a1, b0, b1;
        tf2x32(0u, 1234u, 0u, (unsigned)idx, f0, f1);
        tf2x32(f0, f1, 0u, 0u, a0, a1);      // k1 = block(0,0)
        tf2x32(f0, f1, 0u, 1u, b0, b1);      // k2 = block(0,1)
        g_keys[idx][0] = a0; g_keys[idx][1] = a1;
        g_keys[idx][2] = b0; g_keys[idx][3] = b1;
    }
}

// ---------------- big per-step pass: syn gen + Scum update + a^T Scum ----------
__global__ void __launch_bounds__(256, 3) k_step_big(int t) {
    const int b  = blockIdx.x;                       // 0..31
    const int j  = blockIdx.y * 256 + threadIdx.x;   // 0..511
    const int i0 = blockIdx.z * IPT;
    __shared__ float sa[IPT];
    if (threadIdx.x < IPT)
        sa[threadIdx.x] = g_A[((size_t)t*NB + b)*NH + i0 + threadIdx.x];
    __syncthreads();

    const unsigned kk0 = g_keys[t][2], kk1 = g_keys[t][3];   // k2 (syn)
    const bool first = (t == 0);
    float acc = 0.f;
    const unsigned ebase = (unsigned)((b*NH + i0)*NH + j);
    float* sc = g_Scum + ((size_t)b*NH + i0)*NH + j;

#pragma unroll 2
    for (int ii = 0; ii < IPT; ++ii) {
        float s = first ? 0.f : sc[ii*NH];
        unsigned o0, o1;
        tf2x32(kk0, kk1, 0u, ebase + (unsigned)(ii*NH), o0, o1);
        float n = bits_to_normal(o0 ^ o1);
        acc = fmaf(sa[ii], s, acc);          // uses Scum BEFORE this step's syn
        sc[ii*NH] = s + n;
    }
    g_rpart[((size_t)blockIdx.z*NB + b)*NH + j] = acc;

    // neuron noise for this step (k1), generated once (z==0 covers all b,j)
    if (blockIdx.z == 0 && t >= 16) {
        unsigned o0, o1;
        tf2x32(g_keys[t][0], g_keys[t][1], 0u, (unsigned)(b*NH + j), o0, o1);
        g_neu[b*NH + j] = bits_to_normal(o0 ^ o1);
    }
}

// ---------------- small per-step pass: h update --------------------------------
__global__ void __launch_bounds__(128) k_step_small(
        int t, const float* __restrict__ xsig,
        const float* __restrict__ b_hh, const float* __restrict__ alpha,
        const float* __restrict__ beta, float* __restrict__ out_hl,
        float* __restrict__ out_hidden) {
    const int b = blockIdx.x;                        // 0..31
    const int j = blockIdx.y * 128 + threadIdx.x;    // 0..511
    __shared__ float s_a[NH];
    __shared__ float s_x[NI];
    __shared__ float s_c[NT];

    const float* At = &g_A[((size_t)t*NB + b)*NH];
    for (int i = threadIdx.x; i < NH; i += 128) s_a[i] = At[i];
    if (threadIdx.x < NI) s_x[threadIdx.x] = xsig[((size_t)b*NT + t)*NI + threadIdx.x];
    __syncthreads();

    // Hebbian coefficients c_s = a_t . a_s, s < t
    {
        int w = threadIdx.x >> 5, lane = threadIdx.x & 31;
        for (int s = w; s < t; s += 4) {
            const float* As = &g_A[((size_t)s*NB + b)*NH];
            float d = 0.f;
            for (int i = lane; i < NH; i += 32) d = fmaf(s_a[i], As[i], d);
            for (int m = 16; m; m >>= 1) d += __shfl_xor_sync(0xffffffffu, d, m);
            if (lane == 0) s_c[s] = d;
        }
    }
    __syncthreads();

    // a @ w_hh^T  (4 independent accumulator chains)
    float c0 = 0.f, c1 = 0.f, c2 = 0.f, c3 = 0.f;
#pragma unroll 4
    for (int i = 0; i < NH; i += 4) {
        c0 = fmaf(s_a[i+0], g_whhT[(i+0)*NH + j], c0);
        c1 = fmaf(s_a[i+1], g_whhT[(i+1)*NH + j], c1);
        c2 = fmaf(s_a[i+2], g_whhT[(i+2)*NH + j], c2);
        c3 = fmaf(s_a[i+3], g_whhT[(i+3)*NH + j], c3);
    }
    float acc = (c0 + c1) + (c2 + c3);

    // x_t @ w_in^T
    float x0 = 0.f, x1 = 0.f;
#pragma unroll 8
    for (int k = 0; k < NI; k += 2) {
        x0 = fmaf(s_x[k],   g_winT[k*NH + j],     x0);
        x1 = fmaf(s_x[k+1], g_winT[(k+1)*NH + j], x1);
    }
    float xin = x0 + x1;

    // Hebbian part of dj_act
    float hb = 0.f;
    for (int s = 0; s < t; ++s)
        hb = fmaf(s_c[s], g_A[((size_t)s*NB + b)*NH + j], hb);

    // noise part of dj_act (sum chunked partials)
    float r = 0.f;
#pragma unroll
    for (int ch = 0; ch < ICH; ++ch) r += g_rpart[((size_t)ch*NB + b)*NH + j];

    float bj = beta[j];
    float dj = bj * fmaf(0.002f * sqrtf(bj), r, -hb);
    float tmp = acc + xin + b_hh[j] + dj;
    float al = alpha[j];
    float h = (1.0f - al) * g_h[b*NH + j] + al * tmp;
    if (t >= 16) h += 0.05f * sqrtf(al) * g_neu[b*NH + j];

    g_h[b*NH + j] = h;
    out_hl[((size_t)b*NT + t)*NH + j] = h;
    g_A[((size_t)(t+1)*NB + b)*NH + j] = tanhf(h);
    if (t == NT - 1) out_hidden[b*NH + j] = h;
}

// ---------------- final: output_list GEMM --------------------------------------
__global__ void k_out(const float* __restrict__ w_out,
                      const float* __restrict__ hl,
                      float* __restrict__ out_ol) {
    int idx = blockIdx.x * blockDim.x + threadIdx.x;     // 32*64*16
    if (idx >= NB*NT*NO) return;
    int o = idx & (NO-1);
    int bt = idx >> 4;
    const float* hr = &hl[(size_t)bt*NH];
    const float* wr = &w_out[o*NH];
    float a0 = 0.f, a1 = 0.f;
#pragma unroll 8
    for (int jj = 0; jj < NH; jj += 2) {
        a0 = fmaf(hr[jj],   wr[jj],   a0);
        a1 = fmaf(hr[jj+1], wr[jj+1], a1);
    }
    out_ol[idx] = a0 + a1;
}

// ---------------- final: assemble new_j -----------------------------------------
__global__ void __launch_bounds__(512) k_newj(const float* __restrict__ w_hh,
                                              const float* __restrict__ beta,
                                              float* __restrict__ out_nj) {
    const int b   = blockIdx.x;          // 0..31
    const int it0 = blockIdx.y * 8;      // i tile of 8
    const int j   = threadIdx.x;         // 0..511
    __shared__ float sAi[NT*8];
    for (int v = threadIdx.x; v < NT*8; v += 512) {
        int tt = v >> 3, il = v & 7;
        sAi[v] = g_A[((size_t)tt*NB + b)*NH + it0 + il];
    }
    __syncthreads();
    float acc[8];
#pragma unroll
    for (int il = 0; il < 8; ++il) acc[il] = 0.f;
    for (int tt = 0; tt < NT; ++tt) {
        float aj = g_A[((size_t)tt*NB + b)*NH + j];
#pragma unroll
        for (int il = 0; il < 8; ++il) acc[il] = fmaf(sAi[tt*8 + il], aj, acc[il]);
    }
    float bj = beta[j];
    float cs = 0.002f * sqrtf(bj);
#pragma unroll
    for (int il = 0; il < 8; ++il) {
        int i = it0 + il;
        size_t idx = ((size_t)b*NH + i)*NH + j;
        out_nj[idx] = w_hh[i*NH + j] + bj * fmaf(cs, g_Scum[idx], -acc[il]);
    }
}

// ---------------- host launch ---------------------------------------------------
extern "C" void kernel_launch(void* const* d_in, const int* in_sizes, int n_in,
                              void* d_out, int out_size) {
    (void)in_sizes; (void)n_in; (void)out_size;
    const float* x      = (const float*)d_in[0];
    const float* hidden = (const float*)d_in[1];
    const float* w_in   = (const float*)d_in[2];
    const float* w_hh   = (const float*)d_in[3];
    const float* b_hh   = (const float*)d_in[4];
    const float* w_out  = (const float*)d_in[5];
    const float* alpha  = (const float*)d_in[6];
    const float* beta   = (const float*)d_in[7];

    float* out    = (float*)d_out;
    float* out_hl = out;                         // [32,64,512]
    float* out_ol = out_hl + (size_t)NB*NT*NH;   // [32,64,16]
    float* out_h  = out_ol + (size_t)NB*NT*NO;   // [32,512]
    float* out_nj = out_h  + (size_t)NB*NH;      // [32,512,512]

    k_init<<<1024, 256>>>(hidden, w_hh, w_in);
    for (int t = 0; t < NT; ++t) {
        k_step_big<<<dim3(NB, 2, ICH), 256>>>(t);
        k_step_small<<<dim3(NB, 4), 128>>>(t, x, b_hh, alpha, beta, out_hl, out_h);
    }
    k_out<<<128, 256>>>(w_out, out_hl, out_ol);
    k_newj<<<dim3(NB, NH/8), 512>>>(w_hh, beta, out_nj);
}

// round 2
// speedup vs baseline: 1.4938x; 1.4938x over previous
#include <cuda_runtime.h>
#include <cstdint>
#include <math.h>

#define NB 32
#define NT 64
#define NI 64
#define NH 512
#define NO 16
#define ICH 8    // i-chunks per step for the big pass
#define IPT 64   // i per chunk (NH/ICH)

// ---------------- persistent device state (no allocations allowed) -------------
__device__ float g_Scum[NB*NH*NH];          // cumulative raw syn normals (33.5MB)
__device__ float g_A[(NT+1)*NB*NH];         // a_t = tanh(h_t) history
__device__ float g_h[NB*NH];                // hidden state
__device__ float g_rpart[ICH*NB*NH];        // partials of a^T(whh + cb*Scum)
__device__ float g_neu[NB*NH];              // neuron noise (raw normals)
__device__ unsigned g_keys[NT][4];          // per-step k1,k2 (threefry keys)
__device__ float g_whhT[NH*NH];             // w_hh transposed (i-major)
__device__ float g_winT[NI*NH];             // w_in transposed (k-major)

// ---------------- JAX threefry2x32 (exact) ------------------------------------
__device__ __forceinline__ void tf2x32(unsigned k0, unsigned k1, unsigned x0, unsigned x1,
                                       unsigned &o0, unsigned &o1) {
    unsigned k2 = k0 ^ k1 ^ 0x1BD11BDAu;
    x0 += k0; x1 += k1;
#define TFR(r) { x0 += x1; x1 = __funnelshift_l(x1, x1, r); x1 ^= x0; }
    TFR(13) TFR(15) TFR(26) TFR(6)
    x0 += k1; x1 += k2 + 1u;
    TFR(17) TFR(29) TFR(16) TFR(24)
    x0 += k2; x1 += k0 + 2u;
    TFR(13) TFR(15) TFR(26) TFR(6)
    x0 += k0; x1 += k1 + 3u;
    TFR(17) TFR(29) TFR(16) TFR(24)
    x0 += k1; x1 += k2 + 4u;
    TFR(13) TFR(15) TFR(26) TFR(6)
    x0 += k2; x1 += k0 + 5u;
#undef TFR
    o0 = x0; o1 = x1;
}

// XLA ErfInv (f32, Giles polynomial)
__device__ __forceinline__ float erfinv_xla(float x) {
    float w = -__logf(fmaf(-x, x, 1.0f));
    float p;
    if (w < 5.0f) {
        w = w - 2.5f;
        p = 2.81022636e-08f;
        p = fmaf(p, w, 3.43273939e-07f);
        p = fmaf(p, w, -3.5233877e-06f);
        p = fmaf(p, w, -4.39150654e-06f);
        p = fmaf(p, w, 0.00021858087f);
        p = fmaf(p, w, -0.00125372503f);
        p = fmaf(p, w, -0.00417768164f);
        p = fmaf(p, w, 0.246640727f);
        p = fmaf(p, w, 1.50140941f);
    } else {
        w = sqrtf(w) - 3.0f;
        p = -0.000200214257f;
        p = fmaf(p, w, 0.000100950558f);
        p = fmaf(p, w, 0.00134934322f);
        p = fmaf(p, w, -0.00367342844f);
        p = fmaf(p, w, 0.00573950773f);
        p = fmaf(p, w, -0.0076224613f);
        p = fmaf(p, w, 0.00943887047f);
        p = fmaf(p, w, 1.00167406f);
        p = fmaf(p, w, 2.83297682f);
    }
    return p * x;
}

// JAX normal(f32): u = bits->[0,1), scaled to [-1+eps, 1), sqrt(2)*erfinv(u)
__device__ __forceinline__ float bits_to_normal(unsigned bits) {
    float f = __uint_as_float((bits >> 9) | 0x3f800000u) - 1.0f;
    float u = fmaf(f, 2.0f, -0.99999994f);
    u = fmaxf(-0.99999994f, u);
    return 1.41421356f * erfinv_xla(u);
}

// ---------------- init: keys, transposes, h/a0 --------------------------------
__global__ void k_init(const float* __restrict__ hidden,
                       const float* __restrict__ w_hh,
                       const float* __restrict__ w_in) {
    int idx = blockIdx.x * blockDim.x + threadIdx.x;
    if (idx < NH*NH) {                       // w_hhT[i][j] = w_hh[j][i]
        int jj = idx / NH, ii = idx % NH;
        g_whhT[ii*NH + jj] = w_hh[idx];
    }
    if (idx < NI*NH) {                       // w_inT[k][j] = w_in[j][k]
        int jj = idx / NI, kk = idx % NI;
        g_winT[kk*NH + jj] = w_in[idx];
    }
    if (idx < NB*NH) {
        float h = hidden[idx];
        g_h[idx] = h;
        g_A[idx] = tanhf(h);                 // a_0
    }
    if (idx < NT) {
        // fold_in(key(1234), t) -> split -> (k1, k2); partitionable foldlike split
        unsigned f0, f1, a0, a1, b0, b1;
        tf2x32(0u, 1234u, 0u, (unsigned)idx, f0, f1);
        tf2x32(f0, f1, 0u, 0u, a0, a1);      // k1 = block(0,0)
        tf2x32(f0, f1, 0u, 1u, b0, b1);      // k2 = block(0,1)
        g_keys[idx][0] = a0; g_keys[idx][1] = a1;
        g_keys[idx][2] = b0; g_keys[idx][3] = b1;
    }
}

// ------- big per-step pass: syn gen + Scum update + a^T(whh + cb*Scum) --------
__global__ void __launch_bounds__(256, 4) k_step_big(int t, const float* __restrict__ beta) {
    const int b  = blockIdx.x;                       // 0..31
    const int j  = blockIdx.y * 256 + threadIdx.x;   // 0..511
    const int i0 = blockIdx.z * IPT;
    __shared__ float sa[IPT];
    if (threadIdx.x < IPT)
        sa[threadIdx.x] = g_A[((size_t)t*NB + b)*NH + i0 + threadIdx.x];
    __syncthreads();

    const float bj = beta[j];
    const float cb = 0.002f * bj * sqrtf(bj);        // beta * sigma_syn * sqrt(beta)
    const unsigned kk0 = g_keys[t][2], kk1 = g_keys[t][3];   // k2 (syn)
    const bool first = (t == 0);
    float acc = 0.f;
    const unsigned ebase = (unsigned)((b*NH + i0)*NH + j);
    float* sc = g_Scum + ((size_t)b*NH + i0)*NH + j;
    const float* wr = g_whhT + (size_t)i0*NH + j;

#pragma unroll 2
    for (int ii = 0; ii < IPT; ii += 2) {
        float s0 = first ? 0.f : sc[ii*NH];
        float s1 = first ? 0.f : sc[(ii+1)*NH];
        float w0 = wr[ii*NH];
        float w1 = wr[(ii+1)*NH];
        unsigned a0, a1, c0, c1;
        tf2x32(kk0, kk1, 0u, ebase + (unsigned)(ii*NH),     a0, a1);
        tf2x32(kk0, kk1, 0u, ebase + (unsigned)((ii+1)*NH), c0, c1);
        float n0 = bits_to_normal(a0 ^ a1);
        float n1 = bits_to_normal(c0 ^ c1);
        acc = fmaf(sa[ii],   fmaf(cb, s0, w0), acc);   // uses Scum BEFORE syn update
        acc = fmaf(sa[ii+1], fmaf(cb, s1, w1), acc);
        sc[ii*NH]     = s0 + n0;
        sc[(ii+1)*NH] = s1 + n1;
    }
    g_rpart[((size_t)blockIdx.z*NB + b)*NH + j] = acc;

    // neuron noise for this step (k1), generated once (z==0 covers all b,j)
    if (blockIdx.z == 0 && t >= 16) {
        unsigned o0, o1;
        tf2x32(g_keys[t][0], g_keys[t][1], 0u, (unsigned)(b*NH + j), o0, o1);
        g_neu[b*NH + j] = bits_to_normal(o0 ^ o1);
    }
}

// ---------------- small per-step pass: h update --------------------------------
__global__ void __launch_bounds__(256) k_step_small(
        int t, const float* __restrict__ xsig,
        const float* __restrict__ b_hh, const float* __restrict__ alpha,
        const float* __restrict__ beta, float* __restrict__ out_hl,
        float* __restrict__ out_hidden) {
    const int b = blockIdx.x;                        // 0..31
    const int j = blockIdx.y * 256 + threadIdx.x;    // 0..511
    __shared__ float s_a[NH];
    __shared__ float s_x[NI];
    __shared__ float s_c[NT];

    const float* At = &g_A[((size_t)t*NB + b)*NH];
    for (int i = threadIdx.x; i < NH; i += 256) s_a[i] = At[i];
    if (threadIdx.x < NI) s_x[threadIdx.x] = xsig[((size_t)b*NT + t)*NI + threadIdx.x];
    __syncthreads();

    // Hebbian coefficients c_s = a_t . a_s, s < t (8 warps)
    {
        int w = threadIdx.x >> 5, lane = threadIdx.x & 31;
        for (int s = w; s < t; s += 8) {
            const float* As = &g_A[((size_t)s*NB + b)*NH];
            float d = 0.f;
            for (int i = lane; i < NH; i += 32) d = fmaf(s_a[i], As[i], d);
            for (int m = 16; m; m >>= 1) d += __shfl_xor_sync(0xffffffffu, d, m);
            if (lane == 0) s_c[s] = d;
        }
    }
    __syncthreads();

    // x_t @ w_in^T
    float x0 = 0.f, x1 = 0.f;
#pragma unroll 8
    for (int k = 0; k < NI; k += 2) {
        x0 = fmaf(s_x[k],   g_winT[k*NH + j],     x0);
        x1 = fmaf(s_x[k+1], g_winT[(k+1)*NH + j], x1);
    }
    float xin = x0 + x1;

    // Hebbian part of dj_act
    float hb = 0.f;
    for (int s = 0; s < t; ++s)
        hb = fmaf(s_c[s], g_A[((size_t)s*NB + b)*NH + j], hb);

    // combined a@whhT + cb*(a^T Scum): sum chunked partials
    float comb = 0.f;
#pragma unroll
    for (int ch = 0; ch < ICH; ++ch) comb += g_rpart[((size_t)ch*NB + b)*NH + j];

    float bj = beta[j];
    float tmp = xin + b_hh[j] + comb - bj * hb;
    float al = alpha[j];
    float h = (1.0f - al) * g_h[b*NH + j] + al * tmp;
    if (t >= 16) h += 0.05f * sqrtf(al) * g_neu[b*NH + j];

    g_h[b*NH + j] = h;
    out_hl[((size_t)b*NT + t)*NH + j] = h;
    g_A[((size_t)(t+1)*NB + b)*NH + j] = tanhf(h);
    if (t == NT - 1) out_hidden[b*NH + j] = h;
}

// ---------------- final: output_list GEMM --------------------------------------
__global__ void k_out(const float* __restrict__ w_out,
                      const float* __restrict__ hl,
                      float* __restrict__ out_ol) {
    int idx = blockIdx.x * blockDim.x + threadIdx.x;     // 32*64*16
    if (idx >= NB*NT*NO) return;
    int o = idx & (NO-1);
    int bt = idx >> 4;
    const float* hr = &hl[(size_t)bt*NH];
    const float* wr = &w_out[o*NH];
    float a0 = 0.f, a1 = 0.f;
#pragma unroll 8
    for (int jj = 0; jj < NH; jj += 2) {
        a0 = fmaf(hr[jj],   wr[jj],   a0);
        a1 = fmaf(hr[jj+1], wr[jj+1], a1);
    }
    out_ol[idx] = a0 + a1;
}

// ---------------- final: assemble new_j -----------------------------------------
__global__ void __launch_bounds__(512) k_newj(const float* __restrict__ w_hh,
                                              const float* __restrict__ beta,
                                              float* __restrict__ out_nj) {
    const int b   = blockIdx.x;          // 0..31
    const int it0 = blockIdx.y * 8;      // i tile of 8
    const int j   = threadIdx.x;         // 0..511
    __shared__ float sAi[NT*8];
    for (int v = threadIdx.x; v < NT*8; v += 512) {
        int tt = v >> 3, il = v & 7;
        sAi[v] = g_A[((size_t)tt*NB + b)*NH + it0 + il];
    }
    __syncthreads();
    float acc[8];
#pragma unroll
    for (int il = 0; il < 8; ++il) acc[il] = 0.f;
    for (int tt = 0; tt < NT; ++tt) {
        float aj = g_A[((size_t)tt*NB + b)*NH + j];
#pragma unroll
        for (int il = 0; il < 8; ++il) acc[il] = fmaf(sAi[tt*8 + il], aj, acc[il]);
    }
    float bj = beta[j];
    float cs = 0.002f * sqrtf(bj);
#pragma unroll
    for (int il = 0; il < 8; ++il) {
        int i = it0 + il;
        size_t idx = ((size_t)b*NH + i)*NH + j;
        out_nj[idx] = w_hh[i*NH + j] + bj * fmaf(cs, g_Scum[idx], -acc[il]);
    }
}

// ---------------- host launch ---------------------------------------------------
extern "C" void kernel_launch(void* const* d_in, const int* in_sizes, int n_in,
                              void* d_out, int out_size) {
    (void)in_sizes; (void)n_in; (void)out_size;
    const float* x      = (const float*)d_in[0];
    const float* hidden = (const float*)d_in[1];
    const float* w_in   = (const float*)d_in[2];
    const float* w_hh   = (const float*)d_in[3];
    const float* b_hh   = (const float*)d_in[4];
    const float* w_out  = (const float*)d_in[5];
    const float* alpha  = (const float*)d_in[6];
    const float* beta   = (const float*)d_in[7];

    float* out    = (float*)d_out;
    float* out_hl = out;                         // [32,64,512]
    float* out_ol = out_hl + (size_t)NB*NT*NH;   // [32,64,16]
    float* out_h  = out_ol + (size_t)NB*NT*NO;   // [32,512]
    float* out_nj = out_h  + (size_t)NB*NH;      // [32,512,512]

    k_init<<<1024, 256>>>(hidden, w_hh, w_in);
    for (int t = 0; t < NT; ++t) {
        k_step_big<<<dim3(NB, 2, ICH), 256>>>(t, beta);
        k_step_small<<<dim3(NB, 2), 256>>>(t, x, b_hh, alpha, beta, out_hl, out_h);
    }
    k_out<<<128, 256>>>(w_out, out_hl, out_ol);
    k_newj<<<dim3(NB, NH/8), 512>>>(w_hh, beta, out_nj);
}

// round 4
// speedup vs baseline: 1.6847x; 1.1278x over previous
#include <cuda_runtime.h>
#include <cstdint>
#include <math.h>

#define NB 32
#define NT 64
#define NI 64
#define NH 512
#define NO 16
#define ICH 16   // i-chunks per step for the big pass
#define IPT 32   // i per chunk (NH/ICH)

// ---------------- persistent device state (no allocations allowed) -------------
__device__ float g_Scum[NB*NH*NH];          // cumulative raw syn normals (33.5MB)
__device__ float g_A[(NT+1)*NB*NH];         // a_t = tanh(h_t) history
__device__ float g_h[NB*NH];                // hidden state
__device__ float g_rpart[ICH*NB*NH];        // partials of a^T(whh + cb*Scum)
__device__ unsigned g_keys[NT][4];          // per-step k1,k2 (threefry keys)
__device__ float g_whhT[NH*NH];             // w_hh transposed (i-major)
__device__ float g_winT[NI*NH];             // w_in transposed (k-major)

// ---------------- JAX threefry2x32 (exact) ------------------------------------
__device__ __forceinline__ void tf2x32(unsigned k0, unsigned k1, unsigned x0, unsigned x1,
                                       unsigned &o0, unsigned &o1) {
    unsigned k2 = k0 ^ k1 ^ 0x1BD11BDAu;
    x0 += k0; x1 += k1;
#define TFR(r) { x0 += x1; x1 = __funnelshift_l(x1, x1, r); x1 ^= x0; }
    TFR(13) TFR(15) TFR(26) TFR(6)
    x0 += k1; x1 += k2 + 1u;
    TFR(17) TFR(29) TFR(16) TFR(24)
    x0 += k2; x1 += k0 + 2u;
    TFR(13) TFR(15) TFR(26) TFR(6)
    x0 += k0; x1 += k1 + 3u;
    TFR(17) TFR(29) TFR(16) TFR(24)
    x0 += k1; x1 += k2 + 4u;
    TFR(13) TFR(15) TFR(26) TFR(6)
    x0 += k2; x1 += k0 + 5u;
#undef TFR
    o0 = x0; o1 = x1;
}

// 4 interleaved threefry streams sharing one key (counters differ) — high ILP
__device__ __forceinline__ void tf2x32_x4(unsigned k0, unsigned k1,
                                          unsigned c0, unsigned c1, unsigned c2, unsigned c3,
                                          unsigned* bits) {
    unsigned k2 = k0 ^ k1 ^ 0x1BD11BDAu;
    unsigned a0 = k0 + 0u, b0 = k1 + c0;
    unsigned a1 = k0 + 0u, b1 = k1 + c1;
    unsigned a2 = k0 + 0u, b2 = k1 + c2;
    unsigned a3 = k0 + 0u, b3 = k1 + c3;
#define TFR4(r) { \
    a0 += b0; b0 = __funnelshift_l(b0, b0, r); b0 ^= a0; \
    a1 += b1; b1 = __funnelshift_l(b1, b1, r); b1 ^= a1; \
    a2 += b2; b2 = __funnelshift_l(b2, b2, r); b2 ^= a2; \
    a3 += b3; b3 = __funnelshift_l(b3, b3, r); b3 ^= a3; }
#define INJ4(ka, kb, n) { \
    a0 += ka; b0 += kb + n; a1 += ka; b1 += kb + n; \
    a2 += ka; b2 += kb + n; a3 += ka; b3 += kb + n; }
    TFR4(13) TFR4(15) TFR4(26) TFR4(6)
    INJ4(k1, k2, 1u)
    TFR4(17) TFR4(29) TFR4(16) TFR4(24)
    INJ4(k2, k0, 2u)
    TFR4(13) TFR4(15) TFR4(26) TFR4(6)
    INJ4(k0, k1, 3u)
    TFR4(17) TFR4(29) TFR4(16) TFR4(24)
    INJ4(k1, k2, 4u)
    TFR4(13) TFR4(15) TFR4(26) TFR4(6)
    INJ4(k2, k0, 5u)
#undef TFR4
#undef INJ4
    bits[0] = a0 ^ b0; bits[1] = a1 ^ b1; bits[2] = a2 ^ b2; bits[3] = a3 ^ b3;
}

// XLA ErfInv (f32, Giles polynomial)
__device__ __forceinline__ float erfinv_xla(float x) {
    float w = -__logf(fmaf(-x, x, 1.0f));
    float p;
    if (w < 5.0f) {
        w = w - 2.5f;
        p = 2.81022636e-08f;
        p = fmaf(p, w, 3.43273939e-07f);
        p = fmaf(p, w, -3.5233877e-06f);
        p = fmaf(p, w, -4.39150654e-06f);
        p = fmaf(p, w, 0.00021858087f);
        p = fmaf(p, w, -0.00125372503f);
        p = fmaf(p, w, -0.00417768164f);
        p = fmaf(p, w, 0.246640727f);
        p = fmaf(p, w, 1.50140941f);
    } else {
        w = sqrtf(w) - 3.0f;
        p = -0.000200214257f;
        p = fmaf(p, w, 0.000100950558f);
        p = fmaf(p, w, 0.00134934322f);
        p = fmaf(p, w, -0.00367342844f);
        p = fmaf(p, w, 0.00573950773f);
        p = fmaf(p, w, -0.0076224613f);
        p = fmaf(p, w, 0.00943887047f);
        p = fmaf(p, w, 1.00167406f);
        p = fmaf(p, w, 2.83297682f);
    }
    return p * x;
}

// JAX normal(f32): u in [-0.99999994, 1), sqrt(2)*erfinv(u)
__device__ __forceinline__ float bits_to_normal(unsigned bits) {
    float f = __uint_as_float((bits >> 9) | 0x3f800000u) - 1.0f;
    float u = fmaf(f, 1.99999994f, -0.99999994f);
    u = fmaxf(-0.99999994f, u);
    return 1.41421356f * erfinv_xla(u);
}

// ---------------- init: keys, transposes, h/a0 --------------------------------
__global__ void k_init(const float* __restrict__ hidden,
                       const float* __restrict__ w_hh,
                       const float* __restrict__ w_in) {
    int idx = blockIdx.x * blockDim.x + threadIdx.x;
    if (idx < NH*NH) {                       // w_hhT[i][j] = w_hh[j][i]
        int jj = idx / NH, ii = idx % NH;
        g_whhT[ii*NH + jj] = w_hh[idx];
    }
    if (idx < NI*NH) {                       // w_inT[k][j] = w_in[j][k]
        int jj = idx / NI, kk = idx % NI;
        g_winT[kk*NH + jj] = w_in[idx];
    }
    if (idx < NB*NH) {
        float h = hidden[idx];
        g_h[idx] = h;
        g_A[idx] = tanhf(h);                 // a_0
    }
    if (idx < NT) {
        // fold_in(key(1234), t) -> split -> (k1, k2); partitionable foldlike split
        unsigned f0, f1, a0, a1, b0, b1;
        tf2x32(0u, 1234u, 0u, (unsigned)idx, f0, f1);
        tf2x32(f0, f1, 0u, 0u, a0, a1);      // k1 = block(0,0)
        tf2x32(f0, f1, 0u, 1u, b0, b1);      // k2 = block(0,1)
        g_keys[idx][0] = a0; g_keys[idx][1] = a1;
        g_keys[idx][2] = b0; g_keys[idx][3] = b1;
    }
}

// ------- big per-step pass: syn gen + Scum update + a^T(whh + cb*Scum) --------
template<bool FIRST>
__global__ void __launch_bounds__(256, 5) k_step_big(int t, const float* __restrict__ beta) {
    const int b  = blockIdx.x;                       // 0..31
    const int j  = blockIdx.y * 256 + threadIdx.x;   // 0..511
    const int i0 = blockIdx.z * IPT;
    __shared__ float sa[IPT];
    if (threadIdx.x < IPT)
        sa[threadIdx.x] = g_A[((size_t)t*NB + b)*NH + i0 + threadIdx.x];
    __syncthreads();

    const float bj = beta[j];
    const float cb = 0.002f * bj * sqrtf(bj);        // beta * sigma_syn * sqrt(beta)
    const unsigned kk0 = g_keys[t][2], kk1 = g_keys[t][3];   // k2 (syn)
    float acc = 0.f;
    const unsigned ebase = (unsigned)((b*NH + i0)*NH + j);
    float* sc = g_Scum + ((size_t)b*NH + i0)*NH + j;
    const float* wr = g_whhT + (size_t)i0*NH + j;

#pragma unroll 1
    for (int ii = 0; ii < IPT; ii += 4) {
        float s0, s1, s2, s3;
        if (FIRST) { s0 = s1 = s2 = s3 = 0.f; }
        else {
            s0 = sc[(ii+0)*NH]; s1 = sc[(ii+1)*NH];
            s2 = sc[(ii+2)*NH]; s3 = sc[(ii+3)*NH];
        }
        float w0 = wr[(ii+0)*NH], w1 = wr[(ii+1)*NH];
        float w2 = wr[(ii+2)*NH], w3 = wr[(ii+3)*NH];
        unsigned bits[4];
        unsigned c = ebase + (unsigned)(ii*NH);
        tf2x32_x4(kk0, kk1, c, c + NH, c + 2u*NH, c + 3u*NH, bits);
        float n0 = bits_to_normal(bits[0]);
        float n1 = bits_to_normal(bits[1]);
        float n2 = bits_to_normal(bits[2]);
        float n3 = bits_to_normal(bits[3]);
        acc = fmaf(sa[ii+0], fmaf(cb, s0, w0), acc);   // Scum BEFORE syn update
        acc = fmaf(sa[ii+1], fmaf(cb, s1, w1), acc);
        acc = fmaf(sa[ii+2], fmaf(cb, s2, w2), acc);
        acc = fmaf(sa[ii+3], fmaf(cb, s3, w3), acc);
        sc[(ii+0)*NH] = s0 + n0;
        sc[(ii+1)*NH] = s1 + n1;
        sc[(ii+2)*NH] = s2 + n2;
        sc[(ii+3)*NH] = s3 + n3;
    }
    g_rpart[((size_t)blockIdx.z*NB + b)*NH + j] = acc;
}

// ---------------- small per-step pass: h update + neuron noise -----------------
__global__ void __launch_bounds__(256) k_step_small(
        int t, const float* __restrict__ xsig,
        const float* __restrict__ b_hh, const float* __restrict__ alpha,
        const float* __restrict__ beta, float* __restrict__ out_hl,
        float* __restrict__ out_hidden) {
    const int b = blockIdx.x;                        // 0..31
    const int j = blockIdx.y * 256 + threadIdx.x;    // 0..511
    __shared__ float s_a[NH];
    __shared__ float s_x[NI];
    __shared__ float s_c[NT];

    const float* At = &g_A[((size_t)t*NB + b)*NH];
    for (int i = threadIdx.x; i < NH; i += 256) s_a[i] = At[i];
    if (threadIdx.x < NI) s_x[threadIdx.x] = xsig[((size_t)b*NT + t)*NI + threadIdx.x];
    __syncthreads();

    // Hebbian coefficients c_s = a_t . a_s, s < t (8 warps)
    {
        int w = threadIdx.x >> 5, lane = threadIdx.x & 31;
        for (int s = w; s < t; s += 8) {
            const float* As = &g_A[((size_t)s*NB + b)*NH];
            float d = 0.f;
            for (int i = lane; i < NH; i += 32) d = fmaf(s_a[i], As[i], d);
            for (int m = 16; m; m >>= 1) d += __shfl_xor_sync(0xffffffffu, d, m);
            if (lane == 0) s_c[s] = d;
        }
    }
    __syncthreads();

    // x_t @ w_in^T
    float x0 = 0.f, x1 = 0.f;
#pragma unroll 8
    for (int k = 0; k < NI; k += 2) {
        x0 = fmaf(s_x[k],   g_winT[k*NH + j],     x0);
        x1 = fmaf(s_x[k+1], g_winT[(k+1)*NH + j], x1);
    }
    float xin = x0 + x1;

    // Hebbian part of dj_act
    float hb = 0.f;
    for (int s = 0; s < t; ++s)
        hb = fmaf(s_c[s], g_A[((size_t)s*NB + b)*NH + j], hb);

    // combined a@whhT + cb*(a^T Scum): sum chunked partials
    float comb = 0.f;
#pragma unroll
    for (int ch = 0; ch < ICH; ++ch) comb += g_rpart[((size_t)ch*NB + b)*NH + j];

    float bj = beta[j];
    float tmp = xin + b_hh[j] + comb - bj * hb;
    float al = alpha[j];
    float h = (1.0f - al) * g_h[b*NH + j] + al * tmp;
    if (t >= 16) {
        unsigned o0, o1;
        tf2x32(g_keys[t][0], g_keys[t][1], 0u, (unsigned)(b*NH + j), o0, o1);
        h += 0.05f * sqrtf(al) * bits_to_normal(o0 ^ o1);
    }

    g_h[b*NH + j] = h;
    out_hl[((size_t)b*NT + t)*NH + j] = h;
    g_A[((size_t)(t+1)*NB + b)*NH + j] = tanhf(h);
    if (t == NT - 1) out_hidden[b*NH + j] = h;
}

// ---------------- final: output_list GEMM --------------------------------------
__global__ void k_out(const float* __restrict__ w_out,
                      const float* __restrict__ hl,
                      float* __restrict__ out_ol) {
    int idx = blockIdx.x * blockDim.x + threadIdx.x;     // 32*64*16
    if (idx >= NB*NT*NO) return;
    int o = idx & (NO-1);
    int bt = idx >> 4;
    const float* hr = &hl[(size_t)bt*NH];
    const float* wr = &w_out[o*NH];
    float a0 = 0.f, a1 = 0.f;
#pragma unroll 8
    for (int jj = 0; jj < NH; jj += 2) {
        a0 = fmaf(hr[jj],   wr[jj],   a0);
        a1 = fmaf(hr[jj+1], wr[jj+1], a1);
    }
    out_ol[idx] = a0 + a1;
}

// ---------------- final: assemble new_j -----------------------------------------
__global__ void __launch_bounds__(512) k_newj(const float* __restrict__ w_hh,
                                              const float* __restrict__ beta,
                                              float* __restrict__ out_nj) {
    const int b   = blockIdx.x;          // 0..31
    const int it0 = blockIdx.y * 8;      // i tile of 8
    const int j   = threadIdx.x;         // 0..511
    __shared__ float sAi[NT*8];
    for (int v = threadIdx.x; v < NT*8; v += 512) {
        int tt = v >> 3, il = v & 7;
        sAi[v] = g_A[((size_t)tt*NB + b)*NH + it0 + il];
    }
    __syncthreads();
    float acc[8];
#pragma unroll
    for (int il = 0; il < 8; ++il) acc[il] = 0.f;
    for (int tt = 0; tt < NT; ++tt) {
        float aj = g_A[((size_t)tt*NB + b)*NH + j];
#pragma unroll
        for (int il = 0; il < 8; ++il) acc[il] = fmaf(sAi[tt*8 + il], aj, acc[il]);
    }
    float bj = beta[j];
    float cs = 0.002f * sqrtf(bj);
#pragma unroll
    for (int il = 0; il < 8; ++il) {
        int i = it0 + il;
        size_t idx = ((size_t)b*NH + i)*NH + j;
        out_nj[idx] = w_hh[i*NH + j] + bj * fmaf(cs, g_Scum[idx], -acc[il]);
    }
}

// ---------------- host launch ---------------------------------------------------
extern "C" void kernel_launch(void* const* d_in, const int* in_sizes, int n_in,
                              void* d_out, int out_size) {
    (void)in_sizes; (void)n_in; (void)out_size;
    const float* x      = (const float*)d_in[0];
    const float* hidden = (const float*)d_in[1];
    const float* w_in   = (const float*)d_in[2];
    const float* w_hh   = (const float*)d_in[3];
    const float* b_hh   = (const float*)d_in[4];
    const float* w_out  = (const float*)d_in[5];
    const float* alpha  = (const float*)d_in[6];
    const float* beta   = (const float*)d_in[7];

    float* out    = (float*)d_out;
    float* out_hl = out;                         // [32,64,512]
    float* out_ol = out_hl + (size_t)NB*NT*NH;   // [32,64,16]
    float* out_h  = out_ol + (size_t)NB*NT*NO;   // [32,512]
    float* out_nj = out_h  + (size_t)NB*NH;      // [32,512,512]

    k_init<<<1024, 256>>>(hidden, w_hh, w_in);
    for (int t = 0; t < NT; ++t) {
        if (t == 0) k_step_big<true ><<<dim3(NB, 2, ICH), 256>>>(t, beta);
        else        k_step_big<false><<<dim3(NB, 2, ICH), 256>>>(t, beta);
        k_step_small<<<dim3(NB, 2), 256>>>(t, x, b_hh, alpha, beta, out_hl, out_h);
    }
    k_out<<<128, 256>>>(w_out, out_hl, out_ol);
    k_newj<<<dim3(NB, NH/8), 512>>>(w_hh, beta, out_nj);
}